// round 15
// baseline (speedup 1.0000x reference)
#include <cuda_runtime.h>
#include <cuda_fp16.h>
#include <cstdint>

#define BATCH 16
#define TSEQ  4096
#define DIM   256
#define CH    64
#define NC    (TSEQ/CH)          // 64 chunks

typedef unsigned int u32;
typedef unsigned short u16;
typedef unsigned long long u64;

// ---------------- device scratch (allocation-free rule) ----------------
__device__ float g_E[BATCH * NC * DIM];             // chunk-final LOCAL h
__device__ u64   g_mask[BATCH];                     // per-batch chunk-done bitmask
// B / C pre-converted fp16 in mma fragment layout: [ks16][nt2_16][lane32][slot4]
__device__ __align__(16) u32 g_Bf[32768];
__device__ __align__(16) u32 g_Cf[32768];

// ---------------- helpers ----------------
__device__ __forceinline__ u16 f16_rn(float x) {
    return __half_as_ushort(__float2half_rn(x));
}
__device__ __forceinline__ u32 pack2(u16 a, u16 b) {
    return (u32)a | ((u32)b << 16);
}
__device__ __forceinline__ void mma_f16(float* c, const u32* a, u32 b0, u32 b1) {
    asm("mma.sync.aligned.m16n8k16.row.col.f32.f16.f16.f32 "
        "{%0,%1,%2,%3}, {%4,%5,%6,%7}, {%8,%9}, {%0,%1,%2,%3};"
        : "+f"(c[0]), "+f"(c[1]), "+f"(c[2]), "+f"(c[3])
        : "r"(a[0]), "r"(a[1]), "r"(a[2]), "r"(a[3]), "r"(b0), "r"(b1));
}

// ---------------------------------------------------------------------------
// k0: convert B and C to fp16 fragment layout; zero the chunk masks.
// ---------------------------------------------------------------------------
__global__ void k0_convert(const float* __restrict__ Bm, const float* __restrict__ Cm)
{
    if (blockIdx.x == 0 && threadIdx.x < BATCH) g_mask[threadIdx.x] = 0ull;

    int idx = blockIdx.x * 256 + threadIdx.x;        // 0..32767
    int slot  = idx & 3;
    int lane  = (idx >> 2) & 31;
    int nt2   = (idx >> 7) & 15;
    int ks    = (idx >> 11) & 15;                    // k-step 0..15
    int ntlow = slot >> 1, breg = slot & 1;
    int n = (nt2 * 2 + ntlow) * 8 + (lane >> 2);
    int k = ks * 16 + (lane & 3) * 2 + breg * 8;

    g_Bf[idx] = pack2(f16_rn(Bm[(size_t)k * DIM + n]),
                      f16_rn(Bm[(size_t)(k + 1) * DIM + n]));
    g_Cf[idx] = pack2(f16_rn(Cm[(size_t)k * DIM + n]),
                      f16_rn(Cm[(size_t)(k + 1) * DIM + n]));
}

// ---------------- smem (disjoint regions) ----------------
// scanb: 64 x 260 floats = 66560 B at offset 0
// F    : fp16 A-fragments, 4 slabs x 8KB = 32768 B at offset 66560
#define OFF_F    66560
#define SMEM_SZ  (OFF_F + 32768)      // 99328 B; 2 CTA/SM fits 228KB carveout

// A-frag staging (fp16 rn), slab stride 8KB (2048 u32)
__device__ __forceinline__ void stage_A(u32* F, int row, int cp, float x, float y)
{
    int slab = row >> 4, rin = row & 15;
    int ks = cp >> 3, cpin = cp & 7;
    int lane = (rin & 7) * 4 + (cpin & 3);
    int reg  = ((cpin >> 2) << 1) | (rin >> 3);
    F[slab * 2048 + ((ks * 32 + lane) << 2) + reg] = pack2(f16_rn(x), f16_rn(y));
}

// Mainloop: warp tile m32 x n64 (2 M-slabs), single pass, B fp16 via LDG.
__device__ __forceinline__ void gemm_main(const u32* __restrict__ gBf,
                                          const u32* F,
                                          float acc[2][8][4], int wr, int wc, int lane)
{
    const u32* a0p = F + (wr * 2 + 0) * 2048 + lane * 4;
    const u32* a1p = F + (wr * 2 + 1) * 2048 + lane * 4;
    const u32* b_p = gBf + (wc * 4) * 128 + lane * 4;
    #pragma unroll
    for (int ks = 0; ks < 16; ++ks) {
        uint4 AH0 = *(const uint4*)(a0p + ks * 128);
        uint4 AH1 = *(const uint4*)(a1p + ks * 128);
        u32 ah[2][4] = {{AH0.x, AH0.y, AH0.z, AH0.w}, {AH1.x, AH1.y, AH1.z, AH1.w}};
        const u32* bp = b_p + ks * 2048;
        #pragma unroll
        for (int jp = 0; jp < 2; ++jp) {
            uint4 B0 = *(const uint4*)(bp + (2 * jp) * 128);
            uint4 B1 = *(const uint4*)(bp + (2 * jp + 1) * 128);
            #pragma unroll
            for (int s = 0; s < 2; ++s) {
                mma_f16(acc[s][4 * jp + 0], ah[s], B0.x, B0.y);
                mma_f16(acc[s][4 * jp + 1], ah[s], B0.z, B0.w);
                mma_f16(acc[s][4 * jp + 2], ah[s], B1.x, B1.y);
                mma_f16(acc[s][4 * jp + 3], ah[s], B1.z, B1.w);
            }
        }
    }
}

// ---------------------------------------------------------------------------
// kF: fused  Bu = U@B -> E pass -> publish -> wait -> carry -> exact scan
//     (writes F directly) -> Y = h@C (direct STG).  256 thr, 2 CTA/SM.
//     grid (b=16, c=64): bid = c*16 + b, dependencies have smaller bids.
// ---------------------------------------------------------------------------
__global__ __launch_bounds__(256, 2) void kF(
    const float* __restrict__ U, const float* __restrict__ A,
    const float* __restrict__ h0v, float* __restrict__ Y)
{
    extern __shared__ __align__(16) char smem[];
    float* scanb = (float*)smem;
    u32* F = (u32*)(smem + OFF_F);

    const int tid = threadIdx.x, wid = tid >> 5, lane = tid & 31;
    const int wr = wid & 1, wc = wid >> 1;
    const int b = blockIdx.x, c = blockIdx.y;
    const int t0 = c * CH;

    // ---- stage U tile as fp16 A-fragments (float4 reads, 2 frag writes each)
    {
        const float4* ub = (const float4*)(U + ((size_t)b * TSEQ + t0) * DIM);
        #pragma unroll
        for (int it = 0; it < 16; ++it) {
            int idx = tid + it * 256;          // 4096 = 64 rows x 64 col-quads
            int row = idx >> 6, q = idx & 63;
            float4 v = ub[(size_t)row * 64 + q];
            stage_A(F, row, 2 * q,     v.x, v.y);
            stage_A(F, row, 2 * q + 1, v.z, v.w);
        }
    }
    __syncthreads();

    float acc[2][8][4];
    #pragma unroll
    for (int s = 0; s < 2; ++s)
        #pragma unroll
        for (int i = 0; i < 8; ++i) {
            acc[s][i][0]=0.f; acc[s][i][1]=0.f; acc[s][i][2]=0.f; acc[s][i][3]=0.f;
        }
    gemm_main(g_Bf, F, acc, wr, wc, lane);

    // acc -> scanb (state-major for the scan), float2 stores
    #pragma unroll
    for (int s = 0; s < 2; ++s) {
        int r0 = (wr * 2 + s) * 16 + (lane >> 2);
        #pragma unroll
        for (int a = 0; a < 8; ++a) {
            int col = wc * 64 + (a >> 1) * 16 + (a & 1) * 8 + (lane & 3) * 2;
            *(float2*)(scanb + r0 * 260 + col) =
                make_float2(acc[s][a][0], acc[s][a][1]);
            *(float2*)(scanb + (r0 + 8) * 260 + col) =
                make_float2(acc[s][a][2], acc[s][a][3]);
        }
    }
    __syncthreads();

    // ---- pass 1: local E only (software-pipelined: load 8 ahead)
    const float a = A[tid];
    {
        float h = 0.f;
        float buf[8], nxt[8];
        #pragma unroll
        for (int i = 0; i < 8; ++i) buf[i] = scanb[i * 260 + tid];
        #pragma unroll
        for (int g = 0; g < 8; ++g) {
            if (g < 7) {
                #pragma unroll
                for (int i = 0; i < 8; ++i)
                    nxt[i] = scanb[((g + 1) * 8 + i) * 260 + tid];
            }
            #pragma unroll
            for (int i = 0; i < 8; ++i) h = fmaf(h, a, buf[i]);
            #pragma unroll
            for (int i = 0; i < 8; ++i) buf[i] = nxt[i];
        }
        g_E[((size_t)b * NC + c) * DIM + tid] = h;
    }
    __syncthreads();
    if (tid == 0) {
        __threadfence();
        atomicOr(&g_mask[b], 1ull << c);
    }

    // ---- wait for all earlier chunks of this batch
    const u64 need = (1ull << c) - 1ull;
    if (tid == 0 && need) {
        while ((atomicOr(&g_mask[b], 0ull) & need) != need) __nanosleep(64);
        __threadfence();
    }
    __syncthreads();

    // ---- carry: scan of earlier chunks' E, batched loads (MLP=4)
    float carry = h0v[tid];
    {
        float p = a;
        #pragma unroll
        for (int i = 0; i < 6; ++i) p = p * p;          // a^64
        const float* Eb = g_E + (size_t)b * NC * DIM + tid;
        int j = 0;
        for (; j + 4 <= c; j += 4) {
            float e0 = Eb[(size_t)(j + 0) * DIM];
            float e1 = Eb[(size_t)(j + 1) * DIM];
            float e2 = Eb[(size_t)(j + 2) * DIM];
            float e3 = Eb[(size_t)(j + 3) * DIM];
            carry = fmaf(p, carry, e0);
            carry = fmaf(p, carry, e1);
            carry = fmaf(p, carry, e2);
            carry = fmaf(p, carry, e3);
        }
        for (; j < c; ++j)
            carry = fmaf(p, carry, Eb[(size_t)j * DIM]);
    }

    // ---- pass 2: exact scan seeded with carry; direct u16 frag writes.
    {
        u16* F16 = (u16*)F;
        const int cp = tid >> 1;
        const int half = tid & 1;
        const int ks = cp >> 3, cpin = cp & 7;
        const int lane2base = (cpin & 3);
        const int rsel = ((cpin >> 2) << 1);
        float h = carry;
        float buf[8], nxt[8];
        #pragma unroll
        for (int i = 0; i < 8; ++i) buf[i] = scanb[i * 260 + tid];
        #pragma unroll
        for (int g = 0; g < 8; ++g) {
            if (g < 7) {
                #pragma unroll
                for (int i = 0; i < 8; ++i)
                    nxt[i] = scanb[((g + 1) * 8 + i) * 260 + tid];
            }
            #pragma unroll
            for (int i = 0; i < 8; ++i) {
                int t = g * 8 + i;
                h = fmaf(h, a, buf[i]);
                int slab = t >> 4, rin = t & 15;
                int lane2 = (rin & 7) * 4 + lane2base;
                int reg   = rsel | (rin >> 3);
                F16[(slab * 2048 + ((ks * 32 + lane2) << 2) + reg) * 2 + half] =
                    f16_rn(h);
            }
            #pragma unroll
            for (int i = 0; i < 8; ++i) buf[i] = nxt[i];
        }
    }
    __syncthreads();

    // ---- GEMM with C
    #pragma unroll
    for (int s = 0; s < 2; ++s)
        #pragma unroll
        for (int i = 0; i < 8; ++i) {
            acc[s][i][0]=0.f; acc[s][i][1]=0.f; acc[s][i][2]=0.f; acc[s][i][3]=0.f;
        }
    gemm_main(g_Cf, F, acc, wr, wc, lane);

    // ---- epilogue: store acc directly to Y (float2, full-sector STG)
    {
        float* yb = Y + ((size_t)b * TSEQ + t0) * DIM;
        #pragma unroll
        for (int s = 0; s < 2; ++s) {
            int r0 = (wr * 2 + s) * 16 + (lane >> 2);
            #pragma unroll
            for (int aa = 0; aa < 8; ++aa) {
                int col = wc * 64 + (aa >> 1) * 16 + (aa & 1) * 8 + (lane & 3) * 2;
                *(float2*)(yb + (size_t)r0 * DIM + col) =
                    make_float2(acc[s][aa][0], acc[s][aa][1]);
                *(float2*)(yb + (size_t)(r0 + 8) * DIM + col) =
                    make_float2(acc[s][aa][2], acc[s][aa][3]);
            }
        }
    }
}

// ---------------------------------------------------------------------------

extern "C" void kernel_launch(void* const* d_in, const int* in_sizes, int n_in,
                              void* d_out, int out_size)
{
    const float* U  = (const float*)d_in[0];
    const float* A  = (const float*)d_in[1];
    const float* Bm = (const float*)d_in[2];
    const float* Cm = (const float*)d_in[3];
    const float* h0 = (const float*)d_in[4];
    float* Y = (float*)d_out;
    (void)in_sizes; (void)n_in; (void)out_size;

    cudaFuncSetAttribute(kF, cudaFuncAttributeMaxDynamicSharedMemorySize, SMEM_SZ);

    k0_convert<<<128, 256>>>(Bm, Cm);
    kF<<<dim3(BATCH, NC), 256, SMEM_SZ>>>(U, A, h0, Y);
}

// round 16
// speedup vs baseline: 1.0228x; 1.0228x over previous
#include <cuda_runtime.h>
#include <cuda_fp16.h>
#include <cstdint>

#define BATCH 16
#define TSEQ  4096
#define DIM   256
#define CH    64
#define NC    (TSEQ/CH)          // 64 chunks

typedef unsigned int u32;
typedef unsigned short u16;
typedef unsigned long long u64;

// ---------------- device scratch (allocation-free rule) ----------------
__device__ float g_E[BATCH * NC * DIM];             // chunk-final LOCAL h
__device__ u64   g_mask[BATCH];                     // per-batch chunk-done bitmask
// B / C pre-converted fp16 in mma fragment layout: [ks16][nt2_16][lane32][slot4]
__device__ __align__(16) u32 g_Bf[32768];
__device__ __align__(16) u32 g_Cf[32768];

// ---------------- helpers ----------------
__device__ __forceinline__ u16 f16_rn(float x) {
    return __half_as_ushort(__float2half_rn(x));
}
__device__ __forceinline__ u32 pack2(u16 a, u16 b) {
    return (u32)a | ((u32)b << 16);
}
__device__ __forceinline__ void mma_f16(float* c, const u32* a, u32 b0, u32 b1) {
    asm("mma.sync.aligned.m16n8k16.row.col.f32.f16.f16.f32 "
        "{%0,%1,%2,%3}, {%4,%5,%6,%7}, {%8,%9}, {%0,%1,%2,%3};"
        : "+f"(c[0]), "+f"(c[1]), "+f"(c[2]), "+f"(c[3])
        : "r"(a[0]), "r"(a[1]), "r"(a[2]), "r"(a[3]), "r"(b0), "r"(b1));
}

// ---------------------------------------------------------------------------
// k0: convert B and C to fp16 fragment layout via smem transpose.
// 32 blocks: bid<16 -> B k-slab bid, else C k-slab (bid-16). Coalesced LDG+STG.
// ---------------------------------------------------------------------------
__global__ void k0_convert(const float* __restrict__ Bm, const float* __restrict__ Cm)
{
    __shared__ u32 sT[256][9];            // [n][k-pair], padded (9216 B)
    if (blockIdx.x == 0 && threadIdx.x < BATCH) g_mask[threadIdx.x] = 0ull;

    const float* src = (blockIdx.x < 16) ? Bm : Cm;
    u32* dst         = (blockIdx.x < 16) ? g_Bf : g_Cf;
    const int ks  = blockIdx.x & 15;
    const int tid = threadIdx.x;
    u16* sT16 = (u16*)sT;                 // index = n*18 + kk

    // coalesced load of rows k in [16ks, 16ks+16), fp16 transpose into smem
    const float4* s4 = (const float4*)(src + (size_t)ks * 16 * DIM);
    #pragma unroll
    for (int i = 0; i < 4; ++i) {
        int idx = tid + i * 256;          // 0..1023 = 16 rows x 64 quads
        int kk = idx >> 6, q = idx & 63;
        float4 v = s4[idx];
        sT16[(4 * q + 0) * 18 + kk] = f16_rn(v.x);
        sT16[(4 * q + 1) * 18 + kk] = f16_rn(v.y);
        sT16[(4 * q + 2) * 18 + kk] = f16_rn(v.z);
        sT16[(4 * q + 3) * 18 + kk] = f16_rn(v.w);
    }
    __syncthreads();

    // fragment writes: thread t writes idx = ks*2048 + t + i*256 (coalesced)
    #pragma unroll
    for (int i = 0; i < 8; ++i) {
        int fi = tid + i * 256;           // local frag index 0..2047
        int slot  = fi & 3;
        int lane  = (fi >> 2) & 31;
        int nt2   = (fi >> 7) & 15;
        int ntlow = slot >> 1, breg = slot & 1;
        int n  = (nt2 * 2 + ntlow) * 8 + (lane >> 2);
        int kk = (lane & 3) * 2 + breg * 8;        // always even
        dst[ks * 2048 + fi] = sT[n][kk >> 1];
    }
}

// ---------------- smem (disjoint regions) ----------------
// scanb: 64 x 260 floats = 66560 B at offset 0
// F    : fp16 A-fragments, 4 slabs x 8KB = 32768 B at offset 66560
#define OFF_F    66560
#define SMEM_SZ  (OFF_F + 32768)      // 99328 B; 2 CTA/SM fits 228KB carveout

// A-frag staging (fp16 rn), slab stride 8KB (2048 u32)
__device__ __forceinline__ void stage_A(u32* F, int row, int cp, float x, float y)
{
    int slab = row >> 4, rin = row & 15;
    int ks = cp >> 3, cpin = cp & 7;
    int lane = (rin & 7) * 4 + (cpin & 3);
    int reg  = ((cpin >> 2) << 1) | (rin >> 3);
    F[slab * 2048 + ((ks * 32 + lane) << 2) + reg] = pack2(f16_rn(x), f16_rn(y));
}

// Mainloop: warp tile m32 x n64 (2 M-slabs), single pass, B fp16 via LDG.
__device__ __forceinline__ void gemm_main(const u32* __restrict__ gBf,
                                          const u32* F,
                                          float acc[2][8][4], int wr, int wc, int lane)
{
    const u32* a0p = F + (wr * 2 + 0) * 2048 + lane * 4;
    const u32* a1p = F + (wr * 2 + 1) * 2048 + lane * 4;
    const u32* b_p = gBf + (wc * 4) * 128 + lane * 4;
    #pragma unroll
    for (int ks = 0; ks < 16; ++ks) {
        uint4 AH0 = *(const uint4*)(a0p + ks * 128);
        uint4 AH1 = *(const uint4*)(a1p + ks * 128);
        u32 ah[2][4] = {{AH0.x, AH0.y, AH0.z, AH0.w}, {AH1.x, AH1.y, AH1.z, AH1.w}};
        const u32* bp = b_p + ks * 2048;
        #pragma unroll
        for (int jp = 0; jp < 2; ++jp) {
            uint4 B0 = *(const uint4*)(bp + (2 * jp) * 128);
            uint4 B1 = *(const uint4*)(bp + (2 * jp + 1) * 128);
            #pragma unroll
            for (int s = 0; s < 2; ++s) {
                mma_f16(acc[s][4 * jp + 0], ah[s], B0.x, B0.y);
                mma_f16(acc[s][4 * jp + 1], ah[s], B0.z, B0.w);
                mma_f16(acc[s][4 * jp + 2], ah[s], B1.x, B1.y);
                mma_f16(acc[s][4 * jp + 3], ah[s], B1.z, B1.w);
            }
        }
    }
}

// ---------------------------------------------------------------------------
// kF: fused  Bu = U@B -> E pass -> publish -> wait -> carry -> exact scan
//     (writes F directly) -> Y = h@C (direct STG).  256 thr, 2 CTA/SM.
//     grid (b=16, c=64): bid = c*16 + b, dependencies have smaller bids.
// ---------------------------------------------------------------------------
__global__ __launch_bounds__(256, 2) void kF(
    const float* __restrict__ U, const float* __restrict__ A,
    const float* __restrict__ h0v, float* __restrict__ Y)
{
    extern __shared__ __align__(16) char smem[];
    float* scanb = (float*)smem;
    u32* F = (u32*)(smem + OFF_F);

    const int tid = threadIdx.x, wid = tid >> 5, lane = tid & 31;
    const int wr = wid & 1, wc = wid >> 1;
    const int b = blockIdx.x, c = blockIdx.y;
    const int t0 = c * CH;

    // ---- stage U tile as fp16 A-fragments (float2 reads, as in R14)
    {
        const float* ub = U + ((size_t)b * TSEQ + t0) * DIM;
        #pragma unroll
        for (int it = 0; it < 32; ++it) {
            int idx = tid + it * 256;          // 8192 = 64 rows x 128 colpairs
            int row = idx >> 7, cp = idx & 127;
            float2 v = *(const float2*)(ub + (size_t)row * DIM + cp * 2);
            stage_A(F, row, cp, v.x, v.y);
        }
    }
    __syncthreads();

    float acc[2][8][4];
    #pragma unroll
    for (int s = 0; s < 2; ++s)
        #pragma unroll
        for (int i = 0; i < 8; ++i) {
            acc[s][i][0]=0.f; acc[s][i][1]=0.f; acc[s][i][2]=0.f; acc[s][i][3]=0.f;
        }
    gemm_main(g_Bf, F, acc, wr, wc, lane);

    // acc -> scanb (state-major for the scan), float2 stores
    #pragma unroll
    for (int s = 0; s < 2; ++s) {
        int r0 = (wr * 2 + s) * 16 + (lane >> 2);
        #pragma unroll
        for (int a = 0; a < 8; ++a) {
            int col = wc * 64 + (a >> 1) * 16 + (a & 1) * 8 + (lane & 3) * 2;
            *(float2*)(scanb + r0 * 260 + col) =
                make_float2(acc[s][a][0], acc[s][a][1]);
            *(float2*)(scanb + (r0 + 8) * 260 + col) =
                make_float2(acc[s][a][2], acc[s][a][3]);
        }
    }
    __syncthreads();

    // ---- pass 1: local E only (software-pipelined: load 8 ahead)
    const float a = A[tid];
    {
        float h = 0.f;
        float buf[8], nxt[8];
        #pragma unroll
        for (int i = 0; i < 8; ++i) buf[i] = scanb[i * 260 + tid];
        #pragma unroll
        for (int g = 0; g < 8; ++g) {
            if (g < 7) {
                #pragma unroll
                for (int i = 0; i < 8; ++i)
                    nxt[i] = scanb[((g + 1) * 8 + i) * 260 + tid];
            }
            #pragma unroll
            for (int i = 0; i < 8; ++i) h = fmaf(h, a, buf[i]);
            #pragma unroll
            for (int i = 0; i < 8; ++i) buf[i] = nxt[i];
        }
        g_E[((size_t)b * NC + c) * DIM + tid] = h;
    }
    __syncthreads();
    if (tid == 0) {
        __threadfence();
        atomicOr(&g_mask[b], 1ull << c);
    }

    // ---- wait for all earlier chunks of this batch
    const u64 need = (1ull << c) - 1ull;
    if (tid == 0 && need) {
        while ((atomicOr(&g_mask[b], 0ull) & need) != need) __nanosleep(64);
        __threadfence();
    }
    __syncthreads();

    // ---- carry: scan of earlier chunks' E, batched loads (MLP=4)
    float carry = h0v[tid];
    {
        float p = a;
        #pragma unroll
        for (int i = 0; i < 6; ++i) p = p * p;          // a^64
        const float* Eb = g_E + (size_t)b * NC * DIM + tid;
        int j = 0;
        for (; j + 4 <= c; j += 4) {
            float e0 = Eb[(size_t)(j + 0) * DIM];
            float e1 = Eb[(size_t)(j + 1) * DIM];
            float e2 = Eb[(size_t)(j + 2) * DIM];
            float e3 = Eb[(size_t)(j + 3) * DIM];
            carry = fmaf(p, carry, e0);
            carry = fmaf(p, carry, e1);
            carry = fmaf(p, carry, e2);
            carry = fmaf(p, carry, e3);
        }
        for (; j < c; ++j)
            carry = fmaf(p, carry, Eb[(size_t)j * DIM]);
    }

    // ---- pass 2: exact scan seeded with carry; frag writes via lane-pair shfl
    {
        const int cp = tid >> 1;
        const int ks = cp >> 3, cpin = cp & 7;
        const int lbase = (cpin & 3);
        const int rsel  = ((cpin >> 2) << 1);
        float h = carry;
        float buf[8], nxt[8];
        #pragma unroll
        for (int i = 0; i < 8; ++i) buf[i] = scanb[i * 260 + tid];
        #pragma unroll
        for (int g = 0; g < 8; ++g) {
            if (g < 7) {
                #pragma unroll
                for (int i = 0; i < 8; ++i)
                    nxt[i] = scanb[((g + 1) * 8 + i) * 260 + tid];
            }
            #pragma unroll
            for (int i = 0; i < 8; ++i) {
                int t = g * 8 + i;
                h = fmaf(h, a, buf[i]);
                u32 mine = f16_rn(h);
                u32 part = __shfl_xor_sync(0xffffffffu, mine, 1);
                if (!(tid & 1)) {
                    int slab = t >> 4, rin = t & 15;
                    int lane2 = (rin & 7) * 4 + lbase;
                    int reg   = rsel | (rin >> 3);
                    F[slab * 2048 + ((ks * 32 + lane2) << 2) + reg] =
                        pack2((u16)mine, (u16)part);
                }
            }
            #pragma unroll
            for (int i = 0; i < 8; ++i) buf[i] = nxt[i];
        }
    }
    __syncthreads();

    // ---- GEMM with C
    #pragma unroll
    for (int s = 0; s < 2; ++s)
        #pragma unroll
        for (int i = 0; i < 8; ++i) {
            acc[s][i][0]=0.f; acc[s][i][1]=0.f; acc[s][i][2]=0.f; acc[s][i][3]=0.f;
        }
    gemm_main(g_Cf, F, acc, wr, wc, lane);

    // ---- epilogue: store acc directly to Y (float2, full-sector STG)
    {
        float* yb = Y + ((size_t)b * TSEQ + t0) * DIM;
        #pragma unroll
        for (int s = 0; s < 2; ++s) {
            int r0 = (wr * 2 + s) * 16 + (lane >> 2);
            #pragma unroll
            for (int aa = 0; aa < 8; ++aa) {
                int col = wc * 64 + (aa >> 1) * 16 + (aa & 1) * 8 + (lane & 3) * 2;
                *(float2*)(yb + (size_t)r0 * DIM + col) =
                    make_float2(acc[s][aa][0], acc[s][aa][1]);
                *(float2*)(yb + (size_t)(r0 + 8) * DIM + col) =
                    make_float2(acc[s][aa][2], acc[s][aa][3]);
            }
        }
    }
}

// ---------------------------------------------------------------------------

extern "C" void kernel_launch(void* const* d_in, const int* in_sizes, int n_in,
                              void* d_out, int out_size)
{
    const float* U  = (const float*)d_in[0];
    const float* A  = (const float*)d_in[1];
    const float* Bm = (const float*)d_in[2];
    const float* Cm = (const float*)d_in[3];
    const float* h0 = (const float*)d_in[4];
    float* Y = (float*)d_out;
    (void)in_sizes; (void)n_in; (void)out_size;

    cudaFuncSetAttribute(kF, cudaFuncAttributeMaxDynamicSharedMemorySize, SMEM_SZ);

    k0_convert<<<32, 256>>>(Bm, Cm);
    kF<<<dim3(BATCH, NC), 256, SMEM_SZ>>>(U, A, h0, Y);
}